// round 12
// baseline (speedup 1.0000x reference)
#include <cuda_runtime.h>

// Problem constants (fixed by the reference).
#define B_DIM   16384
#define T_DIM   512
#define HOR     32
#define NSTEP   (T_DIM + B_DIM - 1)   // 16895 scan steps
#define NPAD    16896                 // 132 * 128
#define NBLK    132                   // chunks of 128 steps (= queue depth M)

// Scratch (__device__ globals; zero-initialized).
__device__ float g_ts[NPAD];
__device__ float g_xnorm[NPAD];
__device__ float g_levels[NPAD];
__device__ float g_sseq[NPAD];
__device__ int   g_prog;              // published xnorm progress (blocks done)
__device__ int   g_exit;              // worker exit counter (self-cleaning)

__device__ __forceinline__ float frcp(float x) {
    float r;
    asm("rcp.approx.ftz.f32 %0, %1;" : "=f"(r) : "f"(x));
    return r;
}

// ---------------------------------------------------------------------------
// Kernel 1: parallel gather of the effective series (proven, 4.8us).
// ts[i] = x[0,i,0] (i<512) else x[i-511,511,0]; pad -> 1.
// ---------------------------------------------------------------------------
__global__ void prep_kernel(const float* __restrict__ x) {
    int i = blockIdx.x * blockDim.x + threadIdx.x;
    if (i < NPAD) {
        float v;
        if (i < T_DIM)       v = __ldg(x + i);
        else if (i < NSTEP)  v = __ldg(x + (i - (T_DIM - 1)) * T_DIM + (T_DIM - 1));
        else                 v = 1.0f;
        g_ts[i] = v;
    }
}

// Warp-0 scan body (EXACT R10 body: the proven-fast configuration).
#define SCAN_BODY(BLK, PIDX)                                                   \
  {                                                                            \
    const int base = (BLK) * 128 + t0;                                         \
    const float4 yf = *reinterpret_cast<const float4*>(g_ts + (PIDX));         \
    const float t1raw = fmaf(k, c2, c3);                                       \
    const float t2e   = fmaf(k, c0, c1);                                       \
    const float t1    = (lane == 0) ? fmaf(k4, Tc, t1raw) : t1raw;             \
    float I = fmaf(k2, t2e, t1);                                               \
    float tsh;                                                                 \
    tsh = __shfl_up_sync(FULL, I, 1);  if (lane >= 1)  I = fmaf(K0,  tsh, I);  \
    tsh = __shfl_up_sync(FULL, I, 2);  if (lane >= 2)  I = fmaf(K1,  tsh, I);  \
    tsh = __shfl_up_sync(FULL, I, 4);  if (lane >= 4)  I = fmaf(K2c, tsh, I);  \
    tsh = __shfl_up_sync(FULL, I, 8);  if (lane >= 8)  I = fmaf(K3,  tsh, I);  \
    tsh = __shfl_up_sync(FULL, I, 16); if (lane >= 16) I = fmaf(K4,  tsh, I);  \
    const float l3 = I;                                                        \
    const float l2 = fmaf(rk, l3, ncrk3);                                      \
    const float l1 = fmaf(rk, l2, ncrk2);                                      \
    const float l0 = fmaf(rk, l1, ncrk1);                                      \
    const float d1 = fmaf(os1, l1, gy1);                                       \
    const float rd1 = frcp(d1);                                                \
    const float d0 = fmaf(os0, l0, gy0);                                       \
    const float rd0 = frcp(d0);                                                \
    const float d2 = fmaf(os2, l2, gy2);                                       \
    const float d3 = fmaf(os3, l3, gy3);                                       \
    const float rd2 = frcp(d2), rd3 = frcp(d3);                                \
    const float nc0 = (ay0 * l0) * rd0, nc1 = (ay1 * l1) * rd1;                \
    const float nc2 = (ay2 * l2) * rd2, nc3 = (ay3 * l3) * rd3;                \
    Tc = __shfl_sync(FULL, I, 31);                                             \
    const float rl0 = frcp(l0), rl1 = frcp(l1), rl2 = frcp(l2), rl3 = frcp(l3);\
    const float sn0 = d0 * rl0, sn1 = d1 * rl1, sn2 = d2 * rl2, sn3 = d3 * rl3;\
    *reinterpret_cast<float4*>(g_levels + base) = make_float4(l0, l1, l2, l3); \
    *reinterpret_cast<float4*>(g_sseq   + base) = make_float4(sn0, sn1, sn2, sn3); \
    os0 = omg * sn0; os1 = omg * sn1; os2 = omg * sn2; os3 = omg * sn3;        \
    c0 = nc0; c1 = nc1; c2 = nc2; c3 = nc3;                                    \
    ncrk1 = -(nc1 * rk); ncrk2 = -(nc2 * rk); ncrk3 = -(nc3 * rk);             \
    gy0 = rga * ay0; gy1 = rga * ay1; gy2 = rga * ay2; gy3 = rga * ay3;        \
    ay0 = a * ynn.x; ay1 = a * ynn.y; ay2 = a * ynn.z; ay3 = a * ynn.w;        \
    ynn = yf;                                                                  \
  }

// ---------------------------------------------------------------------------
// Kernel 2: fused scan + out. Grid = 133 x 256, all resident (<=148 SMs).
//  block 0, warp 0 : R10 scanner — NO global synchronization whatsoever.
//  block 0, warp 1 : xnorm consumer (R10) + fire-and-forget g_prog publish
//                    every 4 blocks (it has ~90% idle slack).
//  blocks 1..132   : out workers — spin on g_prog (free: idle SMs), then
//                    stream their slice of out. Last worker resets flags.
// ---------------------------------------------------------------------------
__global__ void __launch_bounds__(256, 1)
fused_kernel(const float* __restrict__ alpha, const float* __restrict__ gamma,
             const float* __restrict__ init_s, const float* __restrict__ level0,
             float* __restrict__ out) {
    const int bid = blockIdx.x;
    const int tid = threadIdx.x;
    const unsigned FULL = 0xFFFFFFFFu;

    if (bid != 0) {
        // ======================= out worker w = bid =======================
        const int w = bid;
        const int chunk_d = (125 * w + 510) >> 7;          // last chunk denorm needs
        const int thr = min(NBLK, max(w + 4, chunk_d + 1));
        if (tid == 0) {
            const volatile int* vp = (const volatile int*)&g_prog;
            while (*vp < thr) { }
        }
        __syncthreads();
        __threadfence();                                   // acquire

        // x-part: rows b4 in [32(w-1), 32w) (workers 1..128 only).
        const float4* __restrict__ X4 = reinterpret_cast<const float4*>(g_xnorm);
        const int b4base = 32 * (w - 1);
        if (b4base < 4096) {
            #pragma unroll 2
            for (int p = 0; p < 16; ++p) {
                const int b4 = b4base + 2 * p + (tid >> 7);
                const int q  = tid & 127;
                const int i4 = b4 + q;
                const float4 A = X4[i4];
                float Bx = __shfl_down_sync(FULL, A.x, 1);
                float By = __shfl_down_sync(FULL, A.y, 1);
                float Bz = __shfl_down_sync(FULL, A.z, 1);
                if ((tid & 31) == 31) {                    // seam lane
                    const float4 B = X4[i4 + 1];
                    Bx = B.x; By = B.y; Bz = B.z;
                }
                const int rbase = b4 * 4 * T_DIM + q * 4;
                *reinterpret_cast<float4*>(out + rbase)             = A;
                *reinterpret_cast<float4*>(out + rbase + T_DIM)     = make_float4(A.y, A.z, A.w, Bx);
                *reinterpret_cast<float4*>(out + rbase + 2 * T_DIM) = make_float4(A.z, A.w, Bx, By);
                *reinterpret_cast<float4*>(out + rbase + 3 * T_DIM) = make_float4(A.w, Bx, By, Bz);
            }
        }

        // denorm part: b in [125(w-1), min(16384, 125w)).
        const int bs = 125 * (w - 1);
        const int be = min(B_DIM, 125 * w);
        const int ntask = (be - bs) * 16;
        for (int tt = tid; tt < ntask; tt += 256) {
            const int b = bs + (tt >> 4);
            const int i = tt & 15;
            const float lvl = g_levels[b + (T_DIM - 1)];
            const float sa  = g_sseq[b + 384 + 2 * i];
            const float sb  = g_sseq[b + 385 + 2 * i];
            *reinterpret_cast<float4*>(out + B_DIM * T_DIM + b * (2 * HOR) + 4 * i) =
                make_float4(lvl, sa, lvl, sb);
        }

        // exit protocol: last of the 132 workers resets flags for replay.
        __syncthreads();
        if (tid == 0) {
            __threadfence();
            if (atomicAdd(&g_exit, 1) == NBLK - 1) {
                g_prog = 0;
                g_exit = 0;
            }
        }
        return;
    }

    // ===================== block 0: scan (R10 layout) =====================
    __shared__ int s_cnt;
    const int lane = tid & 31;
    const int t0 = lane * 4;
    if (tid == 0) s_cnt = 0;
    __syncthreads();
    if (tid >= 64) return;                 // warps 2..7 idle out

    if (tid >= 32) {
        // ---- warp 1: x_norm consumer + progress publisher.
        volatile int* vc = &s_cnt;
        #pragma unroll 1
        for (int blk = 0; blk < NBLK; ++blk) {
            while (*vc < blk + 1) { }
            __threadfence_block();
            const int base = blk * 128 + t0;
            float4 y4 = *reinterpret_cast<const float4*>(g_ts + base);
            float4 l4 = *reinterpret_cast<const float4*>(g_levels + base);
            float4 s4 = (blk == 0)
                ? *reinterpret_cast<const float4*>(init_s + t0)
                : *reinterpret_cast<const float4*>(g_sseq + base - 128);
            float4 o;
            o.x = y4.x * frcp(s4.x * l4.x);
            o.y = y4.y * frcp(s4.y * l4.y);
            o.z = y4.z * frcp(s4.z * l4.z);
            o.w = y4.w * frcp(s4.w * l4.w);
            *reinterpret_cast<float4*>(g_xnorm + base) = o;
            if ((blk & 3) == 3) {          // publish (warp 1 has slack)
                __threadfence();
                if (lane == 0) *(volatile int*)&g_prog = blk + 1;
            }
        }
        return;
    }

    // ---- warp 0: scanner (EXACT R10: no global sync anywhere).
    const float a   = alpha[0];
    const float g   = gamma[0];
    const float k   = 1.0f - a;
    const float omg = 1.0f - g;
    const float k2 = k * k, k4 = k2 * k2;
    const float rk = 1.0f / k;
    const float rga = g / a;
    const float K0 = k4, K1 = K0 * K0, K2c = K1 * K1, K3 = K2c * K2c, K4 = K3 * K3;

    float Tc = level0[0];

    float4 yv  = *reinterpret_cast<const float4*>(g_ts + t0);
    float4 ynv = *reinterpret_cast<const float4*>(g_ts + 128 + t0);
    float4 ynn = *reinterpret_cast<const float4*>(g_ts + 256 + t0);

    float4 sv = *reinterpret_cast<const float4*>(init_s + t0);
    float c0 = (a * yv.x) * frcp(sv.x), c1 = (a * yv.y) * frcp(sv.y);
    float c2 = (a * yv.z) * frcp(sv.z), c3 = (a * yv.w) * frcp(sv.w);
    float ncrk1 = -(c1 * rk), ncrk2 = -(c2 * rk), ncrk3 = -(c3 * rk);
    float gy0 = g * yv.x, gy1 = g * yv.y, gy2 = g * yv.z, gy3 = g * yv.w;
    float os0 = omg * sv.x, os1 = omg * sv.y, os2 = omg * sv.z, os3 = omg * sv.w;
    float ay0 = a * ynv.x, ay1 = a * ynv.y, ay2 = a * ynv.z, ay3 = a * ynv.w;

    #pragma unroll 1
    for (int grp = 0; grp < 32; ++grp) {
        #pragma unroll
        for (int u = 0; u < 4; ++u) {
            const int blk = grp * 4 + u;
            SCAN_BODY(blk, blk * 128 + t0 + 384);
        }
        __threadfence_block();
        if (lane == 0) *(volatile int*)&s_cnt = grp * 4 + 4;
    }

    SCAN_BODY(128, 128 * 128 + t0 + 384);
    SCAN_BODY(129, t0);
    SCAN_BODY(130, t0);
    SCAN_BODY(131, t0);
    __threadfence_block();
    if (lane == 0) *(volatile int*)&s_cnt = NBLK;
}

// ---------------------------------------------------------------------------
// Launch. Inputs (metadata order): x, alpha, gamma, init_seasonality, level.
// ---------------------------------------------------------------------------
extern "C" void kernel_launch(void* const* d_in, const int* in_sizes, int n_in,
                              void* d_out, int out_size) {
    const float* x      = (const float*)d_in[0];
    const float* alpha  = (const float*)d_in[1];
    const float* gamma  = (const float*)d_in[2];
    const float* init_s = (const float*)d_in[3];
    const float* level  = (const float*)d_in[4];
    float* out = (float*)d_out;

    prep_kernel<<<NBLK, 128>>>(x);
    fused_kernel<<<NBLK + 1, 256>>>(alpha, gamma, init_s, level, out);
}

// round 14
// speedup vs baseline: 1.6178x; 1.6178x over previous
#include <cuda_runtime.h>

// Problem constants (fixed by the reference).
#define B_DIM   16384
#define T_DIM   512
#define HOR     32
#define NSTEP   (T_DIM + B_DIM - 1)   // 16895 scan steps
#define NPAD    16896                 // 132 * 128
#define NBLK    132                   // chunks of 128 steps (= queue depth M)
#define NHEAD   24                    // chunks self-gathered by block 0
#define NPROD   (NBLK - NHEAD)        // 108 producer blocks (chunks 24..131)

// Scratch (__device__ globals; zero-initialized).
__device__ float g_ts[NPAD];
__device__ float g_xnorm[NPAD];
__device__ float g_levels[NPAD];
__device__ float g_sseq[NPAD];
__device__ int   g_done;              // producer completion counter

__device__ __forceinline__ float frcp(float x) {
    float r;
    asm("rcp.approx.ftz.f32 %0, %1;" : "=f"(r) : "f"(x));
    return r;
}

// Effective series element: ts[i] = x[0,i,0] (i<512) else x[i-511,511,0]; pad->1.
__device__ __forceinline__ float load_ts(const float* __restrict__ x, int i) {
    if (i < T_DIM)  return __ldg(x + i);
    if (i < NSTEP)  return __ldg(x + (i - (T_DIM - 1)) * T_DIM + (T_DIM - 1));
    return 1.0f;
}

// Warp-0 scan body (EXACT R10 body: the proven-fast configuration).
#define SCAN_BODY(BLK, PIDX)                                                   \
  {                                                                            \
    const int base = (BLK) * 128 + t0;                                         \
    const float4 yf = *reinterpret_cast<const float4*>(g_ts + (PIDX));         \
    const float t1raw = fmaf(k, c2, c3);                                       \
    const float t2e   = fmaf(k, c0, c1);                                       \
    const float t1    = (lane == 0) ? fmaf(k4, Tc, t1raw) : t1raw;             \
    float I = fmaf(k2, t2e, t1);                                               \
    float tsh;                                                                 \
    tsh = __shfl_up_sync(FULL, I, 1);  if (lane >= 1)  I = fmaf(K0,  tsh, I);  \
    tsh = __shfl_up_sync(FULL, I, 2);  if (lane >= 2)  I = fmaf(K1,  tsh, I);  \
    tsh = __shfl_up_sync(FULL, I, 4);  if (lane >= 4)  I = fmaf(K2c, tsh, I);  \
    tsh = __shfl_up_sync(FULL, I, 8);  if (lane >= 8)  I = fmaf(K3,  tsh, I);  \
    tsh = __shfl_up_sync(FULL, I, 16); if (lane >= 16) I = fmaf(K4,  tsh, I);  \
    const float l3 = I;                                                        \
    const float l2 = fmaf(rk, l3, ncrk3);                                      \
    const float l1 = fmaf(rk, l2, ncrk2);                                      \
    const float l0 = fmaf(rk, l1, ncrk1);                                      \
    const float d1 = fmaf(os1, l1, gy1);                                       \
    const float rd1 = frcp(d1);                                                \
    const float d0 = fmaf(os0, l0, gy0);                                       \
    const float rd0 = frcp(d0);                                                \
    const float d2 = fmaf(os2, l2, gy2);                                       \
    const float d3 = fmaf(os3, l3, gy3);                                       \
    const float rd2 = frcp(d2), rd3 = frcp(d3);                                \
    const float nc0 = (ay0 * l0) * rd0, nc1 = (ay1 * l1) * rd1;                \
    const float nc2 = (ay2 * l2) * rd2, nc3 = (ay3 * l3) * rd3;                \
    Tc = __shfl_sync(FULL, I, 31);                                             \
    const float rl0 = frcp(l0), rl1 = frcp(l1), rl2 = frcp(l2), rl3 = frcp(l3);\
    const float sn0 = d0 * rl0, sn1 = d1 * rl1, sn2 = d2 * rl2, sn3 = d3 * rl3;\
    *reinterpret_cast<float4*>(g_levels + base) = make_float4(l0, l1, l2, l3); \
    *reinterpret_cast<float4*>(g_sseq   + base) = make_float4(sn0, sn1, sn2, sn3); \
    os0 = omg * sn0; os1 = omg * sn1; os2 = omg * sn2; os3 = omg * sn3;        \
    c0 = nc0; c1 = nc1; c2 = nc2; c3 = nc3;                                    \
    ncrk1 = -(nc1 * rk); ncrk2 = -(nc2 * rk); ncrk3 = -(nc3 * rk);             \
    gy0 = rga * ay0; gy1 = rga * ay1; gy2 = rga * ay2; gy3 = rga * ay3;        \
    ay0 = a * ynn.x; ay1 = a * ynn.y; ay2 = a * ynn.z; ay3 = a * ynn.w;        \
    ynn = yf;                                                                  \
  }

// ---------------------------------------------------------------------------
// Fused gather + scan. Grid = 109 x 256 (all resident; producers never wait).
//  blocks 1..108 : fire-and-forget gather of chunk 23+bid (24..131); one
//                  release fence + one atomicAdd each. No spins anywhere.
//  block 0       : phase A: all 256 threads gather chunks 0..23 (syncthreads)
//                  -> scan iterations 0..20 need no cross-block sync at all.
//    warp 0      : R10 scanner; exactly ONE gpu-scope wait (spin on g_done +
//                  acquire fence) at the group-4/5 boundary.
//    warp 1      : R10 xnorm consumer (cta-scope fences only).
// Scanner resets g_done at the end (producers provably finished).
// ---------------------------------------------------------------------------
__global__ void __launch_bounds__(256, 1)
scan_kernel(const float* __restrict__ x,
            const float* __restrict__ alpha, const float* __restrict__ gamma,
            const float* __restrict__ init_s, const float* __restrict__ level0) {
    const int bid = blockIdx.x;
    const int tid = threadIdx.x;

    if (bid != 0) {
        // ---- producer: chunk j = 23 + bid (never waits on anything).
        const int j = NHEAD - 1 + bid;
        if (tid < 128) g_ts[j * 128 + tid] = load_ts(x, j * 128 + tid);
        __threadfence();                       // release my store
        __syncthreads();
        if (tid == 0) atomicAdd(&g_done, 1);
        return;
    }

    // ================= block 0: phase A self-gather (chunks 0..23) =========
    #pragma unroll
    for (int e = tid; e < NHEAD * 128; e += 256)
        g_ts[e] = load_ts(x, e);
    __shared__ int s_cnt;
    if (tid == 0) s_cnt = 0;
    __syncthreads();
    if (tid >= 64) return;                     // warps 2..7 done

    const unsigned FULL = 0xFFFFFFFFu;
    const int lane = tid & 31;
    const int t0 = lane * 4;

    if (tid >= 32) {
        // ---- warp 1: x_norm consumer (EXACT R10; cta-scope only).
        volatile int* vc = &s_cnt;
        #pragma unroll 1
        for (int blk = 0; blk < NBLK; ++blk) {
            while (*vc < blk + 1) { }
            __threadfence_block();
            const int base = blk * 128 + t0;
            float4 y4 = *reinterpret_cast<const float4*>(g_ts + base);
            float4 l4 = *reinterpret_cast<const float4*>(g_levels + base);
            float4 s4 = (blk == 0)
                ? *reinterpret_cast<const float4*>(init_s + t0)
                : *reinterpret_cast<const float4*>(g_sseq + base - 128);
            float4 o;
            o.x = y4.x * frcp(s4.x * l4.x);
            o.y = y4.y * frcp(s4.y * l4.y);
            o.z = y4.z * frcp(s4.z * l4.z);
            o.w = y4.w * frcp(s4.w * l4.w);
            *reinterpret_cast<float4*>(g_xnorm + base) = o;
        }
        return;
    }

    // ---- warp 0: scanner (R10 body; ONE gpu-scope wait in the whole kernel).
    const float a   = alpha[0];
    const float g   = gamma[0];
    const float k   = 1.0f - a;
    const float omg = 1.0f - g;
    const float k2 = k * k, k4 = k2 * k2;
    const float rk = 1.0f / k;
    const float rga = g / a;
    const float K0 = k4, K1 = K0 * K0, K2c = K1 * K1, K3 = K2c * K2c, K4 = K3 * K3;

    float Tc = level0[0];

    float4 yv  = *reinterpret_cast<const float4*>(g_ts + t0);
    float4 ynv = *reinterpret_cast<const float4*>(g_ts + 128 + t0);
    float4 ynn = *reinterpret_cast<const float4*>(g_ts + 256 + t0);

    float4 sv = *reinterpret_cast<const float4*>(init_s + t0);
    float c0 = (a * yv.x) * frcp(sv.x), c1 = (a * yv.y) * frcp(sv.y);
    float c2 = (a * yv.z) * frcp(sv.z), c3 = (a * yv.w) * frcp(sv.w);
    float ncrk1 = -(c1 * rk), ncrk2 = -(c2 * rk), ncrk3 = -(c3 * rk);
    float gy0 = g * yv.x, gy1 = g * yv.y, gy2 = g * yv.z, gy3 = g * yv.w;
    float os0 = omg * sv.x, os1 = omg * sv.y, os2 = omg * sv.z, os3 = omg * sv.w;
    float ay0 = a * ynv.x, ay1 = a * ynv.y, ay2 = a * ynv.z, ay3 = a * ynv.w;

    // Groups 0..4 (blocks 0..19): prefetch reaches chunk 22 — all phase A.
    #pragma unroll 1
    for (int grp = 0; grp < 5; ++grp) {
        #pragma unroll
        for (int u = 0; u < 4; ++u) {
            const int blk = grp * 4 + u;
            SCAN_BODY(blk, blk * 128 + t0 + 384);
        }
        __threadfence_block();
        if (lane == 0) *(volatile int*)&s_cnt = grp * 4 + 4;
    }

    // The ONE global wait: all producer chunks (24..131) in place.
    {
        const volatile int* vp = (const volatile int*)&g_done;
        while (*vp < NPROD) { }
        __threadfence();                       // acquire (single L1D flush)
    }

    // Groups 5..31 (blocks 20..127): branch-free, unguarded.
    #pragma unroll 1
    for (int grp = 5; grp < 32; ++grp) {
        #pragma unroll
        for (int u = 0; u < 4; ++u) {
            const int blk = grp * 4 + u;
            SCAN_BODY(blk, blk * 128 + t0 + 384);
        }
        __threadfence_block();
        if (lane == 0) *(volatile int*)&s_cnt = grp * 4 + 4;
    }

    // Tail blocks 128..131 (prefetch clamped), final publish.
    SCAN_BODY(128, 128 * 128 + t0 + 384);
    SCAN_BODY(129, t0);
    SCAN_BODY(130, t0);
    SCAN_BODY(131, t0);
    __threadfence_block();
    if (lane == 0) *(volatile int*)&s_cnt = NBLK;

    // Self-clean for graph replay (spin above proves producers finished).
    if (lane == 0) g_done = 0;
}

// ---------------------------------------------------------------------------
// Materialize outputs (proven 9.1us). x-part: window B fetched from the next
// thread via 3 shfl_down; only the seam lane does a real second load.
// ---------------------------------------------------------------------------
#define XTASKS ((B_DIM / 4) * (T_DIM / 4))     // 524288
#define DTASKS (B_DIM * (HOR / 2))             // 262144

__global__ void __launch_bounds__(256)
out_kernel(float* __restrict__ out) {
    const unsigned FULL = 0xFFFFFFFFu;
    const float4* __restrict__ X4 = reinterpret_cast<const float4*>(g_xnorm);
    int gid = blockIdx.x * blockDim.x + threadIdx.x;
    if (gid < XTASKS) {
        const int b4 = gid >> 7;
        const int q  = gid & 127;
        const int i4 = b4 + q;
        const float4 A = X4[i4];
        float Bx = __shfl_down_sync(FULL, A.x, 1);
        float By = __shfl_down_sync(FULL, A.y, 1);
        float Bz = __shfl_down_sync(FULL, A.z, 1);
        if ((threadIdx.x & 31) == 31) {
            const float4 B = X4[i4 + 1];
            Bx = B.x; By = B.y; Bz = B.z;
        }
        const int rbase = (b4 * 4) * T_DIM + q * 4;
        *reinterpret_cast<float4*>(out + rbase)             = A;
        *reinterpret_cast<float4*>(out + rbase + T_DIM)     = make_float4(A.y, A.z, A.w, Bx);
        *reinterpret_cast<float4*>(out + rbase + 2 * T_DIM) = make_float4(A.z, A.w, Bx, By);
        *reinterpret_cast<float4*>(out + rbase + 3 * T_DIM) = make_float4(A.w, Bx, By, Bz);
    } else {
        const int j = gid - XTASKS;
        if (j < DTASKS) {
            const int b = j >> 4;
            const int i = j & 15;
            const float lvl = g_levels[b + (T_DIM - 1)];
            const float sa  = g_sseq[b + 384 + 2 * i];
            const float sb  = g_sseq[b + 385 + 2 * i];
            *reinterpret_cast<float4*>(out + B_DIM * T_DIM + b * (2 * HOR) + 4 * i) =
                make_float4(lvl, sa, lvl, sb);
        }
    }
}

// ---------------------------------------------------------------------------
// Launch. Inputs (metadata order): x, alpha, gamma, init_seasonality, level.
// ---------------------------------------------------------------------------
extern "C" void kernel_launch(void* const* d_in, const int* in_sizes, int n_in,
                              void* d_out, int out_size) {
    const float* x      = (const float*)d_in[0];
    const float* alpha  = (const float*)d_in[1];
    const float* gamma  = (const float*)d_in[2];
    const float* init_s = (const float*)d_in[3];
    const float* level  = (const float*)d_in[4];
    float* out = (float*)d_out;

    scan_kernel<<<NPROD + 1, 256>>>(x, alpha, gamma, init_s, level);
    out_kernel<<<(XTASKS + DTASKS) / 256, 256>>>(out);
}